// round 1
// baseline (speedup 1.0000x reference)
#include <cuda_runtime.h>

// Tropical (max-times) matvec: out[b, i] = max_j M[i, j] * x[b, j]
// B = 256 batches, n = 2048.  Treated as C[i,b] = maxplus-GEMM(M[i,j], x[b,j])
// with split-K=2 for full-chip occupancy (128 blocks on 148 SMs).

#define NN      2048   // n
#define NB      256    // batch
#define BM      128    // i-tile per block
#define BN      64     // b-tile per block
#define BK      16     // j-chunk per smem stage
#define TM      8      // i per thread
#define TN      4      // b per thread
#define SPLIT   2
#define KPER    (NN / SPLIT)   // 1024 j's per block
#define NITER   (KPER / BK)    // 64
#define THREADS 256

// Scratch for split-K partials: [SPLIT][NB][NN] = 4 MB
__device__ float g_part[SPLIT * NB * NN];

__global__ __launch_bounds__(THREADS, 1)
void trop_mm_kernel(const float* __restrict__ x, const float* __restrict__ M)
{
    __shared__ float Ms[2][BK][BM + 4];   // Ms[buf][j][i_local]
    __shared__ float Xs[2][BK][BN + 4];   // Xs[buf][j][b_local]

    const int tid = threadIdx.x;
    const int tx  = tid & 15;    // b direction (16 cols)
    const int ty  = tid >> 4;    // i direction (16 rows)
    const int i0  = blockIdx.x * BM;
    const int b0  = blockIdx.y * BN;
    const int k0  = blockIdx.z * KPER;

    // ---- loader coordinates ----
    // M tile: 128 i x 16 j = 512 float4 (along j); thread handles f = tid and tid+256
    const int m_il = tid >> 2;          // 0..63 (second load adds +64)
    const int m_j4 = (tid & 3) * 4;     // 0,4,8,12
    // x tile: 64 b x 16 j = 256 float4; thread handles f = tid
    const int x_bl = tid >> 2;          // 0..63
    const int x_j4 = (tid & 3) * 4;

    const float* Mg = M + (long)(i0 + m_il) * NN + k0 + m_j4;
    const float* Xg = x + (long)(b0 + x_bl) * NN + k0 + x_j4;

    float4 mr0, mr1, xr;

    // ---- prologue: stage kt = 0 ----
    mr0 = *(const float4*)(Mg);
    mr1 = *(const float4*)(Mg + (long)64 * NN);
    xr  = *(const float4*)(Xg);

    Ms[0][m_j4 + 0][m_il]      = mr0.x;
    Ms[0][m_j4 + 1][m_il]      = mr0.y;
    Ms[0][m_j4 + 2][m_il]      = mr0.z;
    Ms[0][m_j4 + 3][m_il]      = mr0.w;
    Ms[0][m_j4 + 0][m_il + 64] = mr1.x;
    Ms[0][m_j4 + 1][m_il + 64] = mr1.y;
    Ms[0][m_j4 + 2][m_il + 64] = mr1.z;
    Ms[0][m_j4 + 3][m_il + 64] = mr1.w;
    Xs[0][x_j4 + 0][x_bl]      = xr.x;
    Xs[0][x_j4 + 1][x_bl]      = xr.y;
    Xs[0][x_j4 + 2][x_bl]      = xr.z;
    Xs[0][x_j4 + 3][x_bl]      = xr.w;
    __syncthreads();

    const float NEG_INF = __int_as_float(0xff800000);
    float acc[TM][TN];
    #pragma unroll
    for (int a = 0; a < TM; a++)
        #pragma unroll
        for (int c = 0; c < TN; c++)
            acc[a][c] = NEG_INF;

    for (int kt = 0; kt < NITER; kt++) {
        const int buf = kt & 1;

        // issue next tile's global loads early (latency hidden by compute)
        if (kt + 1 < NITER) {
            const float* Mg2 = Mg + (kt + 1) * BK;
            mr0 = *(const float4*)(Mg2);
            mr1 = *(const float4*)(Mg2 + (long)64 * NN);
            xr  = *(const float4*)(Xg + (kt + 1) * BK);
        }

        // compute on current buffer
        #pragma unroll
        for (int kk = 0; kk < BK; kk++) {
            float4 mv0 = *(const float4*)&Ms[buf][kk][ty * TM];
            float4 mv1 = *(const float4*)&Ms[buf][kk][ty * TM + 4];
            float4 xv4 = *(const float4*)&Xs[buf][kk][tx * TN];
            float mv[TM] = {mv0.x, mv0.y, mv0.z, mv0.w,
                            mv1.x, mv1.y, mv1.z, mv1.w};
            float xv[TN] = {xv4.x, xv4.y, xv4.z, xv4.w};
            #pragma unroll
            for (int a = 0; a < TM; a++)
                #pragma unroll
                for (int c = 0; c < TN; c++)
                    acc[a][c] = fmaxf(acc[a][c], mv[a] * xv[c]);
        }

        // stage next tile into the other buffer
        if (kt + 1 < NITER) {
            const int nb = buf ^ 1;
            Ms[nb][m_j4 + 0][m_il]      = mr0.x;
            Ms[nb][m_j4 + 1][m_il]      = mr0.y;
            Ms[nb][m_j4 + 2][m_il]      = mr0.z;
            Ms[nb][m_j4 + 3][m_il]      = mr0.w;
            Ms[nb][m_j4 + 0][m_il + 64] = mr1.x;
            Ms[nb][m_j4 + 1][m_il + 64] = mr1.y;
            Ms[nb][m_j4 + 2][m_il + 64] = mr1.z;
            Ms[nb][m_j4 + 3][m_il + 64] = mr1.w;
            Xs[nb][x_j4 + 0][x_bl]      = xr.x;
            Xs[nb][x_j4 + 1][x_bl]      = xr.y;
            Xs[nb][x_j4 + 2][x_bl]      = xr.z;
            Xs[nb][x_j4 + 3][x_bl]      = xr.w;
        }
        __syncthreads();
    }

    // ---- write partials: layout [split][b][i] (matches d_out [b][i]) ----
    float* outp = g_part + (long)blockIdx.z * NB * NN;
    #pragma unroll
    for (int c = 0; c < TN; c++) {
        const int b = b0 + tx * TN + c;
        float* row = outp + (long)b * NN + i0 + ty * TM;
        *(float4*)(row)     = make_float4(acc[0][c], acc[1][c], acc[2][c], acc[3][c]);
        *(float4*)(row + 4) = make_float4(acc[4][c], acc[5][c], acc[6][c], acc[7][c]);
    }
}

__global__ __launch_bounds__(256, 1)
void combine_kernel(float* __restrict__ out)
{
    const int idx = blockIdx.x * 256 + threadIdx.x;   // float4 index
    const float4* p0 = (const float4*)g_part;
    const float4* p1 = (const float4*)(g_part + (long)NB * NN);
    float4 a = p0[idx];
    float4 b = p1[idx];
    float4 r = make_float4(fmaxf(a.x, b.x), fmaxf(a.y, b.y),
                           fmaxf(a.z, b.z), fmaxf(a.w, b.w));
    ((float4*)out)[idx] = r;
}

extern "C" void kernel_launch(void* const* d_in, const int* in_sizes, int n_in,
                              void* d_out, int out_size)
{
    // x: [256, 2048] (524288), M: [2048, 2048] (4194304) — detect order defensively
    const float* x;
    const float* M;
    if (in_sizes[0] == NB * NN) { x = (const float*)d_in[0]; M = (const float*)d_in[1]; }
    else                        { x = (const float*)d_in[1]; M = (const float*)d_in[0]; }

    dim3 grid(NN / BM, NB / BN, SPLIT);   // 16 x 4 x 2 = 128 blocks
    trop_mm_kernel<<<grid, THREADS>>>(x, M);

    const int n4 = NB * NN / 4;           // 131072 float4
    combine_kernel<<<n4 / 256, 256>>>((float*)d_out);
}